// round 11
// baseline (speedup 1.0000x reference)
#include <cuda_runtime.h>
#include <cuda_bf16.h>

#define IMG_H 512
#define IMG_W 512
#define IMG_HW (IMG_H * IMG_W)
#define OUT_H 510
#define OUT_W 510
#define WIN_PER_WARP 30
#define SEGS 17                              // 17 * 30 = 510 windows per row
#define ROWS_PER_WU 2
#define NROWP (OUT_H / ROWS_PER_WU)          // 255 row-pairs
#define NWU (SEGS * NROWP)                   // 4335 warp-units
#define BLOCK 128
#define NWARP (BLOCK / 32)
#define NBLK ((NWU + NWARP - 1) / NWARP)     // 1084

#define FIX_SCALE 16777216.0                 // 2^24
#define COUNT_SHIFT 52

// Single packed accumulator: bits [52:63] = arrival count, low bits = fixed-point sum.
__device__ unsigned long long g_acc = 0ULL;

// Stat layout: [0:3)=cs, [3:9)=g(00,01,02,11,12,22), [9:12)=sv, [12]=Q,
//              [13:22)=Y(00,01,02,10,11,12,20,21,22)
#define NSTAT 22

__device__ __forceinline__ void row_products(
    const float a0, const float a1, const float a2,
    const float v0, const float v1, const float v2,
    float* __restrict__ p)
{
    p[0] = a0; p[1] = a1; p[2] = a2;
    p[3] = a0 * a0; p[4] = a0 * a1; p[5] = a0 * a2;
    p[6] = a1 * a1; p[7] = a1 * a2; p[8] = a2 * a2;
    p[9] = v0; p[10] = v1; p[11] = v2;
    p[12] = v0 * v0 + v1 * v1 + v2 * v2;
    p[13] = a0 * v0; p[14] = a0 * v1; p[15] = a0 * v2;
    p[16] = a1 * v0; p[17] = a1 * v1; p[18] = a1 * v2;
    p[19] = a2 * v0; p[20] = a2 * v1; p[21] = a2 * v2;
}

__device__ __forceinline__ float epilogue(const float* __restrict__ w)
{
    const float inv9 = 1.0f / 9.0f;
    const float eps9 = 1e-7f / 9.0f;
    const float mu0 = w[0] * inv9, mu1 = w[1] * inv9, mu2 = w[2] * inv9;

    const float g00 = w[3] * inv9 - mu0 * mu0 + eps9;
    const float g01 = w[4] * inv9 - mu0 * mu1;
    const float g02 = w[5] * inv9 - mu0 * mu2;
    const float g11 = w[6] * inv9 - mu1 * mu1 + eps9;
    const float g12 = w[7] * inv9 - mu1 * mu2;
    const float g22 = w[8] * inv9 - mu2 * mu2 + eps9;

    const float adj00 = g11 * g22 - g12 * g12;
    const float adj01 = g02 * g12 - g01 * g22;
    const float adj02 = g01 * g12 - g02 * g11;
    const float adj11 = g00 * g22 - g02 * g02;
    const float adj12 = g01 * g02 - g00 * g12;
    const float adj22 = g00 * g11 - g01 * g01;
    const float det = g00 * adj00 + g01 * adj01 + g02 * adj02;
    const float invdet = 1.0f / det;

    float acc9 = 0.0f;
    #pragma unroll
    for (int cv = 0; cv < 3; cv++) {
        const float s = w[9 + cv];
        const float y0 = w[13 + cv] - mu0 * s;
        const float y1 = w[16 + cv] - mu1 * s;
        const float y2 = w[19 + cv] - mu2 * s;
        const float quad = adj00 * y0 * y0 + adj11 * y1 * y1 + adj22 * y2 * y2
                         + 2.0f * (adj01 * y0 * y1 + adj02 * y0 * y2 + adj12 * y1 * y2);
        acc9 += s * s + quad * invdet;
    }
    return w[12] - acc9 * inv9;
}

__global__ void __launch_bounds__(BLOCK, 8) ml_col2_kernel(
    const float* __restrict__ tgt, const float* __restrict__ sty,
    float* __restrict__ out)
{
    const int tid = threadIdx.x;
    const int lane = tid & 31;
    const int wid = tid >> 5;
    const int wu = blockIdx.x * NWARP + wid;

    float contrib = 0.0f;
    if (wu < NWU) {
        const int rp = wu / SEGS;              // row pair 0..254
        const int seg = wu - rp * SEGS;
        const int row = rp * ROWS_PER_WU;      // top window row
        const int col = seg * WIN_PER_WARP + lane;   // 0..511, in-bounds
        const int base = row * IMG_W + col;

        // ---- 24 coalesced loads: 4 pixel rows x 3 channels x {target, style} ----
        float ta[3][4], sv[3][4];
        #pragma unroll
        for (int ch = 0; ch < 3; ch++) {
            #pragma unroll
            for (int j = 0; j < 4; j++) {
                ta[ch][j] = __ldg(tgt + ch * IMG_HW + base + j * IMG_W);
            }
        }
        #pragma unroll
        for (int ch = 0; ch < 3; ch++) {
            #pragma unroll
            for (int j = 0; j < 4; j++) {
                sv[ch][j] = __ldg(sty + ch * IMG_HW + base + j * IMG_W);
            }
        }

        // ---- Column stats for both window rows; interior rows shared ----
        float A0[NSTAT], A1[NSTAT];
        {
            float p[NSTAT];
            // row 0 -> A0 only
            row_products(ta[0][0], ta[1][0], ta[2][0], sv[0][0], sv[1][0], sv[2][0], p);
            #pragma unroll
            for (int k = 0; k < NSTAT; k++) A0[k] = p[k];
            // rows 1,2 -> both
            row_products(ta[0][1], ta[1][1], ta[2][1], sv[0][1], sv[1][1], sv[2][1], p);
            #pragma unroll
            for (int k = 0; k < NSTAT; k++) { A0[k] += p[k]; A1[k] = p[k]; }
            row_products(ta[0][2], ta[1][2], ta[2][2], sv[0][2], sv[1][2], sv[2][2], p);
            #pragma unroll
            for (int k = 0; k < NSTAT; k++) { A0[k] += p[k]; A1[k] += p[k]; }
            // row 3 -> A1 only
            row_products(ta[0][3], ta[1][3], ta[2][3], sv[0][3], sv[1][3], sv[2][3], p);
            #pragma unroll
            for (int k = 0; k < NSTAT; k++) A1[k] += p[k];
        }

        // ---- Window row 0: horizontal 3-column combine via shuffles, epilogue ----
        {
            float w[NSTAT];
            #pragma unroll
            for (int k = 0; k < NSTAT; k++) {
                const float x1 = __shfl_down_sync(0xFFFFFFFFu, A0[k], 1);
                const float x2 = __shfl_down_sync(0xFFFFFFFFu, A0[k], 2);
                w[k] = A0[k] + x1 + x2;
            }
            if (lane < WIN_PER_WARP) contrib += epilogue(w);
        }
        // ---- Window row 1 ----
        {
            float w[NSTAT];
            #pragma unroll
            for (int k = 0; k < NSTAT; k++) {
                const float x1 = __shfl_down_sync(0xFFFFFFFFu, A1[k], 1);
                const float x2 = __shfl_down_sync(0xFFFFFFFFu, A1[k], 2);
                w[k] = A1[k] + x1 + x2;
            }
            if (lane < WIN_PER_WARP) contrib += epilogue(w);
        }
    }

    // ---- Block reduction: warp shuffles (deterministic fixed tree) ----
    double acc = (double)contrib;
    #pragma unroll
    for (int off = 16; off > 0; off >>= 1)
        acc += __shfl_down_sync(0xFFFFFFFFu, acc, off);

    __shared__ double warp_sums[NWARP];
    if (lane == 0) warp_sums[wid] = acc;
    __syncthreads();

    // ---- Fence-free packed-atomic finish (no release fence -> no L1 flush) ----
    if (tid == 0) {
        double bsum = 0.0;
        #pragma unroll
        for (int i = 0; i < NWARP; i++) bsum += warp_sums[i];

        const long long fx = __double2ll_rn(bsum * FIX_SCALE);
        const unsigned long long term = (1ULL << COUNT_SHIFT) + (unsigned long long)fx;
        const unsigned long long old = atomicAdd(&g_acc, term);

        if ((old >> COUNT_SHIFT) == (unsigned long long)(NBLK - 1)) {
            const unsigned long long total = old + term;
            const long long value =
                (long long)(total - ((unsigned long long)NBLK << COUNT_SHIFT));
            out[0] = (float)((double)value * (1.0 / FIX_SCALE));
            atomicExch(&g_acc, 0ULL);   // reset for next graph replay
        }
    }
}

extern "C" void kernel_launch(void* const* d_in, const int* in_sizes, int n_in,
                              void* d_out, int out_size)
{
    const float* tgt = (const float*)d_in[0];   // target  (3, 512, 512) fp32
    const float* sty = (const float*)d_in[1];   // style   (3, 512, 512) fp32
    float* out = (float*)d_out;

    ml_col2_kernel<<<NBLK, BLOCK>>>(tgt, sty, out);
}

// round 14
// speedup vs baseline: 1.3721x; 1.3721x over previous
#include <cuda_runtime.h>
#include <cuda_bf16.h>

#define IMG_H 512
#define IMG_W 512
#define IMG_HW (IMG_H * IMG_W)
#define OUT_H 510
#define OUT_W 510
#define SEGS 9
#define WPS 62                                // windows per segment strip
#define NWU (SEGS * OUT_H)                    // 4590 warp-units
#define BLOCK 128
#define NWARP (BLOCK / 32)
#define NBLK ((NWU + NWARP - 1) / NWARP)      // 1148

#define FIX_SCALE 16777216.0                  // 2^24
#define COUNT_SHIFT 52

typedef unsigned long long u64;

// Single packed accumulator: bits [52:63] = arrival count, low bits = fixed-point sum.
__device__ u64 g_acc = 0ULL;

// ---- f32x2 packed helpers (sm_103a; ptxas never emits these from C++) ----
__device__ __forceinline__ u64 pk2(float lo, float hi) {
    u64 r; asm("mov.b64 %0,{%1,%2};" : "=l"(r) : "f"(lo), "f"(hi)); return r;
}
__device__ __forceinline__ void upk2(u64 v, float& lo, float& hi) {
    asm("mov.b64 {%0,%1},%2;" : "=f"(lo), "=f"(hi) : "l"(v));
}
__device__ __forceinline__ u64 fma2_(u64 a, u64 b, u64 c) {
    u64 r; asm("fma.rn.f32x2 %0,%1,%2,%3;" : "=l"(r) : "l"(a), "l"(b), "l"(c)); return r;
}
__device__ __forceinline__ u64 add2_(u64 a, u64 b) {
    u64 r; asm("add.rn.f32x2 %0,%1,%2;" : "=l"(r) : "l"(a), "l"(b)); return r;
}
__device__ __forceinline__ u64 mul2_(u64 a, u64 b) {
    u64 r; asm("mul.rn.f32x2 %0,%1,%2;" : "=l"(r) : "l"(a), "l"(b)); return r;
}

// Stat layout (packed pairs, lo=col c, hi=col c+1):
// [0:3)=cs, [3:9)=g(00,01,02,11,12,22), [9:12)=sv, [12]=Q, [13:22)=Y[ch*3+cv]
#define NSTAT 22

__global__ void __launch_bounds__(BLOCK) ml_pk_kernel(
    const float* __restrict__ tgt, const float* __restrict__ sty,
    float* __restrict__ out)
{
    const int tid = threadIdx.x;
    const int lane = tid & 31;
    const int wid = tid >> 5;
    const int wu = blockIdx.x * NWARP + wid;

    float contrib = 0.0f;
    if (wu < NWU) {
        const int rowr = wu / SEGS;              // window row 0..509
        const int seg = wu - rowr * SEGS;
        int colL = seg * WPS + 2 * lane;          // even; this lane's two columns
        if (colL > IMG_W - 2) colL = IMG_W - 2;   // clamp (clamped lanes' windows are masked)
        const int base = rowr * IMG_W + colL;

        // ---- Column-pair statistics over 3 pixel rows (packed f32x2) ----
        u64 S[NSTAT];
        #pragma unroll
        for (int r = 0; r < 3; r++) {
            const u64 a0 = __ldg((const u64*)(tgt + 0 * IMG_HW + base + r * IMG_W));
            const u64 a1 = __ldg((const u64*)(tgt + 1 * IMG_HW + base + r * IMG_W));
            const u64 a2 = __ldg((const u64*)(tgt + 2 * IMG_HW + base + r * IMG_W));
            const u64 v0 = __ldg((const u64*)(sty + 0 * IMG_HW + base + r * IMG_W));
            const u64 v1 = __ldg((const u64*)(sty + 1 * IMG_HW + base + r * IMG_W));
            const u64 v2 = __ldg((const u64*)(sty + 2 * IMG_HW + base + r * IMG_W));
            if (r == 0) {
                S[0] = a0; S[1] = a1; S[2] = a2;
                S[3] = mul2_(a0, a0); S[4] = mul2_(a0, a1); S[5] = mul2_(a0, a2);
                S[6] = mul2_(a1, a1); S[7] = mul2_(a1, a2); S[8] = mul2_(a2, a2);
                S[9] = v0; S[10] = v1; S[11] = v2;
                S[12] = fma2_(v2, v2, fma2_(v1, v1, mul2_(v0, v0)));
                S[13] = mul2_(a0, v0); S[14] = mul2_(a0, v1); S[15] = mul2_(a0, v2);
                S[16] = mul2_(a1, v0); S[17] = mul2_(a1, v1); S[18] = mul2_(a1, v2);
                S[19] = mul2_(a2, v0); S[20] = mul2_(a2, v1); S[21] = mul2_(a2, v2);
            } else {
                S[0] = add2_(S[0], a0); S[1] = add2_(S[1], a1); S[2] = add2_(S[2], a2);
                S[3] = fma2_(a0, a0, S[3]); S[4] = fma2_(a0, a1, S[4]); S[5] = fma2_(a0, a2, S[5]);
                S[6] = fma2_(a1, a1, S[6]); S[7] = fma2_(a1, a2, S[7]); S[8] = fma2_(a2, a2, S[8]);
                S[9] = add2_(S[9], v0); S[10] = add2_(S[10], v1); S[11] = add2_(S[11], v2);
                S[12] = fma2_(v2, v2, fma2_(v1, v1, fma2_(v0, v0, S[12])));
                S[13] = fma2_(a0, v0, S[13]); S[14] = fma2_(a0, v1, S[14]); S[15] = fma2_(a0, v2, S[15]);
                S[16] = fma2_(a1, v0, S[16]); S[17] = fma2_(a1, v1, S[17]); S[18] = fma2_(a1, v2, S[18]);
                S[19] = fma2_(a2, v0, S[19]); S[20] = fma2_(a2, v1, S[20]); S[21] = fma2_(a2, v2, S[21]);
            }
        }

        // ---- Horizontal 3-column combine: 2 shfl + 3 adds per stat -> 2 windows ----
        // Window at col c   : S.lo + S.hi + next.lo
        // Window at col c+1 : S.hi + next.lo + next.hi
        u64 W[NSTAT];
        #pragma unroll
        for (int k = 0; k < NSTAT; k++) {
            float s0, s1;
            upk2(S[k], s0, s1);
            const float n0 = __shfl_down_sync(0xFFFFFFFFu, s0, 1);
            const float n1 = __shfl_down_sync(0xFFFFFFFFu, s1, 1);
            const float t = s1 + n0;
            W[k] = pk2(s0 + t, t + n1);
        }

        // ---- Packed epilogue: both windows at once ----
        const float inv9f = 1.0f / 9.0f;
        const u64 INV9  = pk2(inv9f, inv9f);
        const u64 NINV9 = pk2(-inv9f, -inv9f);
        const u64 EPS9  = pk2(1e-7f * inv9f, 1e-7f * inv9f);
        const u64 NEG1  = pk2(-1.0f, -1.0f);

        const u64 mu0 = mul2_(W[0], INV9), nmu0 = mul2_(W[0], NINV9);
        const u64 mu1 = mul2_(W[1], INV9), nmu1 = mul2_(W[1], NINV9);
        const u64 mu2 = mul2_(W[2], INV9), nmu2 = mul2_(W[2], NINV9);

        const u64 g00 = fma2_(mu0, nmu0, fma2_(W[3], INV9, EPS9));
        const u64 g01 = fma2_(mu0, nmu1, mul2_(W[4], INV9));
        const u64 g02 = fma2_(mu0, nmu2, mul2_(W[5], INV9));
        const u64 g11 = fma2_(mu1, nmu1, fma2_(W[6], INV9, EPS9));
        const u64 g12 = fma2_(mu1, nmu2, mul2_(W[7], INV9));
        const u64 g22 = fma2_(mu2, nmu2, fma2_(W[8], INV9, EPS9));

        const u64 ng01 = mul2_(g01, NEG1);
        const u64 ng02 = mul2_(g02, NEG1);
        const u64 ng11 = mul2_(g11, NEG1);
        const u64 ng12 = mul2_(g12, NEG1);
        const u64 ng22 = mul2_(g22, NEG1);

        const u64 adj00 = fma2_(g12, ng12, mul2_(g11, g22));
        const u64 adj01 = fma2_(g01, ng22, mul2_(g02, g12));   // g02*g12 - g01*g22
        const u64 adj02 = fma2_(g02, ng11, mul2_(g01, g12));   // g01*g12 - g02*g11
        const u64 adj11 = fma2_(g02, ng02, mul2_(g00, g22));
        const u64 adj12 = fma2_(g00, ng12, mul2_(g01, g02));   // g01*g02 - g00*g12
        const u64 adj22 = fma2_(g01, ng01, mul2_(g00, g11));

        const u64 det = fma2_(g00, adj00, fma2_(g01, adj01, mul2_(g02, adj02)));
        float d0, d1;
        upk2(det, d0, d1);
        const u64 invdet = pk2(1.0f / d0, 1.0f / d1);

        u64 acc9 = 0ULL;   // (0.0f, 0.0f)
        #pragma unroll
        for (int cv = 0; cv < 3; cv++) {
            const u64 s = W[9 + cv];
            const u64 y0 = fma2_(nmu0, s, W[13 + cv]);
            const u64 y1 = fma2_(nmu1, s, W[16 + cv]);
            const u64 y2 = fma2_(nmu2, s, W[19 + cv]);
            const u64 y1x2 = add2_(y1, y1);
            const u64 y2x2 = add2_(y2, y2);
            const u64 p0 = fma2_(adj02, y2x2, fma2_(adj01, y1x2, mul2_(adj00, y0)));
            const u64 p1 = fma2_(adj12, y2x2, mul2_(adj11, y1));
            const u64 p2 = mul2_(adj22, y2);
            const u64 quad = fma2_(y2, p2, fma2_(y1, p1, mul2_(y0, p0)));
            acc9 = fma2_(s, s, acc9);
            acc9 = fma2_(quad, invdet, acc9);
        }
        const u64 cpk = fma2_(acc9, NINV9, W[12]);   // Q - acc9/9, both windows

        float c_lo, c_hi;
        upk2(cpk, c_lo, c_hi);
        const int w0 = seg * WPS + 2 * lane;          // unclamped window column
        const bool prod = (lane < 31);                // lane 31 is producer-only
        if (prod && w0 < OUT_W) contrib += c_lo;
        if (prod && w0 + 1 < OUT_W) contrib += c_hi;
    }

    // ---- Block reduction: warp shuffles (deterministic fixed tree) ----
    double acc = (double)contrib;
    #pragma unroll
    for (int off = 16; off > 0; off >>= 1)
        acc += __shfl_down_sync(0xFFFFFFFFu, acc, off);

    __shared__ double warp_sums[NWARP];
    if (lane == 0) warp_sums[wid] = acc;
    __syncthreads();

    // ---- Fence-free packed-atomic finish (no release fence -> no L1 flush) ----
    if (tid == 0) {
        double bsum = 0.0;
        #pragma unroll
        for (int i = 0; i < NWARP; i++) bsum += warp_sums[i];

        const long long fx = __double2ll_rn(bsum * FIX_SCALE);
        const u64 term = (1ULL << COUNT_SHIFT) + (u64)fx;
        const u64 old = atomicAdd(&g_acc, term);

        if ((old >> COUNT_SHIFT) == (u64)(NBLK - 1)) {
            const u64 total = old + term;
            const long long value = (long long)(total - ((u64)NBLK << COUNT_SHIFT));
            out[0] = (float)((double)value * (1.0 / FIX_SCALE));
            atomicExch(&g_acc, 0ULL);   // reset for next graph replay
        }
    }
}

extern "C" void kernel_launch(void* const* d_in, const int* in_sizes, int n_in,
                              void* d_out, int out_size)
{
    const float* tgt = (const float*)d_in[0];   // target  (3, 512, 512) fp32
    const float* sty = (const float*)d_in[1];   // style   (3, 512, 512) fp32
    float* out = (float*)d_out;

    ml_pk_kernel<<<NBLK, BLOCK>>>(tgt, sty, out);
}

// round 15
// speedup vs baseline: 1.4217x; 1.0361x over previous
#include <cuda_runtime.h>
#include <cuda_bf16.h>

#define IMG_H 512
#define IMG_W 512
#define IMG_HW (IMG_H * IMG_W)
#define OUT_H 510
#define OUT_W 510
#define SEGS 9
#define WPS 62                                // windows per segment strip
#define NWU (SEGS * OUT_H)                    // 4590 warp-units
#define BLOCK 128
#define NWARP (BLOCK / 32)
#define NBLK ((NWU + NWARP - 1) / NWARP)      // 1148

#define FIX_SCALE 16777216.0                  // 2^24
#define COUNT_SHIFT 52

typedef unsigned long long u64;

// Single packed accumulator: bits [52:63] = arrival count, low bits = fixed-point sum.
__device__ u64 g_acc = 0ULL;

// ---- f32x2 packed helpers (sm_103a; ptxas never emits these from C++) ----
__device__ __forceinline__ u64 pk2(float lo, float hi) {
    u64 r; asm("mov.b64 %0,{%1,%2};" : "=l"(r) : "f"(lo), "f"(hi)); return r;
}
__device__ __forceinline__ void upk2(u64 v, float& lo, float& hi) {
    asm("mov.b64 {%0,%1},%2;" : "=f"(lo), "=f"(hi) : "l"(v));
}
__device__ __forceinline__ u64 fma2_(u64 a, u64 b, u64 c) {
    u64 r; asm("fma.rn.f32x2 %0,%1,%2,%3;" : "=l"(r) : "l"(a), "l"(b), "l"(c)); return r;
}
__device__ __forceinline__ u64 add2_(u64 a, u64 b) {
    u64 r; asm("add.rn.f32x2 %0,%1,%2;" : "=l"(r) : "l"(a), "l"(b)); return r;
}
__device__ __forceinline__ u64 mul2_(u64 a, u64 b) {
    u64 r; asm("mul.rn.f32x2 %0,%1,%2;" : "=l"(r) : "l"(a), "l"(b)); return r;
}
// Packed negate on the ALU pipe (sign-bit XOR; bit-exact for finite values).
__device__ __forceinline__ u64 neg2_(u64 a) {
    return a ^ 0x8000000080000000ULL;
}

// Stat layout (packed pairs, lo=col c, hi=col c+1):
// [0:3)=cs, [3:9)=g(00,01,02,11,12,22), [9:12)=sv, [12]=Q, [13:22)=Y[ch*3+cv]
#define NSTAT 22

__global__ void __launch_bounds__(BLOCK, 7) ml_pk_kernel(
    const float* __restrict__ tgt, const float* __restrict__ sty,
    float* __restrict__ out)
{
    const int tid = threadIdx.x;
    const int lane = tid & 31;
    const int wid = tid >> 5;
    const int wu = blockIdx.x * NWARP + wid;

    float contrib = 0.0f;
    if (wu < NWU) {
        const int rowr = wu / SEGS;              // window row 0..509
        const int seg = wu - rowr * SEGS;
        int colL = seg * WPS + 2 * lane;          // even; this lane's two columns
        if (colL > IMG_W - 2) colL = IMG_W - 2;   // clamp (clamped lanes' windows are masked)
        const int base = rowr * IMG_W + colL;

        // ---- Software-pipelined loads: rows 0+1 in flight before any products ----
        u64 a0A, a1A, a2A, v0A, v1A, v2A;        // row r
        u64 a0B, a1B, a2B, v0B, v1B, v2B;        // row r+1 (in flight)

        a0A = __ldg((const u64*)(tgt + 0 * IMG_HW + base));
        a1A = __ldg((const u64*)(tgt + 1 * IMG_HW + base));
        a2A = __ldg((const u64*)(tgt + 2 * IMG_HW + base));
        v0A = __ldg((const u64*)(sty + 0 * IMG_HW + base));
        v1A = __ldg((const u64*)(sty + 1 * IMG_HW + base));
        v2A = __ldg((const u64*)(sty + 2 * IMG_HW + base));

        a0B = __ldg((const u64*)(tgt + 0 * IMG_HW + base + IMG_W));
        a1B = __ldg((const u64*)(tgt + 1 * IMG_HW + base + IMG_W));
        a2B = __ldg((const u64*)(tgt + 2 * IMG_HW + base + IMG_W));
        v0B = __ldg((const u64*)(sty + 0 * IMG_HW + base + IMG_W));
        v1B = __ldg((const u64*)(sty + 1 * IMG_HW + base + IMG_W));
        v2B = __ldg((const u64*)(sty + 2 * IMG_HW + base + IMG_W));

        // ---- Products row 0 (init stats) while row-1/row-2 loads fly ----
        u64 S[NSTAT];
        S[0] = a0A; S[1] = a1A; S[2] = a2A;
        S[3] = mul2_(a0A, a0A); S[4] = mul2_(a0A, a1A); S[5] = mul2_(a0A, a2A);
        S[6] = mul2_(a1A, a1A); S[7] = mul2_(a1A, a2A); S[8] = mul2_(a2A, a2A);
        S[9] = v0A; S[10] = v1A; S[11] = v2A;
        S[12] = fma2_(v2A, v2A, fma2_(v1A, v1A, mul2_(v0A, v0A)));
        S[13] = mul2_(a0A, v0A); S[14] = mul2_(a0A, v1A); S[15] = mul2_(a0A, v2A);
        S[16] = mul2_(a1A, v0A); S[17] = mul2_(a1A, v1A); S[18] = mul2_(a1A, v2A);
        S[19] = mul2_(a2A, v0A); S[20] = mul2_(a2A, v1A); S[21] = mul2_(a2A, v2A);

        // Issue row-2 loads (reuse A slots) before consuming row 1.
        a0A = __ldg((const u64*)(tgt + 0 * IMG_HW + base + 2 * IMG_W));
        a1A = __ldg((const u64*)(tgt + 1 * IMG_HW + base + 2 * IMG_W));
        a2A = __ldg((const u64*)(tgt + 2 * IMG_HW + base + 2 * IMG_W));
        v0A = __ldg((const u64*)(sty + 0 * IMG_HW + base + 2 * IMG_W));
        v1A = __ldg((const u64*)(sty + 1 * IMG_HW + base + 2 * IMG_W));
        v2A = __ldg((const u64*)(sty + 2 * IMG_HW + base + 2 * IMG_W));

        // ---- Products row 1 ----
        S[0] = add2_(S[0], a0B); S[1] = add2_(S[1], a1B); S[2] = add2_(S[2], a2B);
        S[3] = fma2_(a0B, a0B, S[3]); S[4] = fma2_(a0B, a1B, S[4]); S[5] = fma2_(a0B, a2B, S[5]);
        S[6] = fma2_(a1B, a1B, S[6]); S[7] = fma2_(a1B, a2B, S[7]); S[8] = fma2_(a2B, a2B, S[8]);
        S[9] = add2_(S[9], v0B); S[10] = add2_(S[10], v1B); S[11] = add2_(S[11], v2B);
        S[12] = fma2_(v2B, v2B, fma2_(v1B, v1B, fma2_(v0B, v0B, S[12])));
        S[13] = fma2_(a0B, v0B, S[13]); S[14] = fma2_(a0B, v1B, S[14]); S[15] = fma2_(a0B, v2B, S[15]);
        S[16] = fma2_(a1B, v0B, S[16]); S[17] = fma2_(a1B, v1B, S[17]); S[18] = fma2_(a1B, v2B, S[18]);
        S[19] = fma2_(a2B, v0B, S[19]); S[20] = fma2_(a2B, v1B, S[20]); S[21] = fma2_(a2B, v2B, S[21]);

        // ---- Products row 2 ----
        S[0] = add2_(S[0], a0A); S[1] = add2_(S[1], a1A); S[2] = add2_(S[2], a2A);
        S[3] = fma2_(a0A, a0A, S[3]); S[4] = fma2_(a0A, a1A, S[4]); S[5] = fma2_(a0A, a2A, S[5]);
        S[6] = fma2_(a1A, a1A, S[6]); S[7] = fma2_(a1A, a2A, S[7]); S[8] = fma2_(a2A, a2A, S[8]);
        S[9] = add2_(S[9], v0A); S[10] = add2_(S[10], v1A); S[11] = add2_(S[11], v2A);
        S[12] = fma2_(v2A, v2A, fma2_(v1A, v1A, fma2_(v0A, v0A, S[12])));
        S[13] = fma2_(a0A, v0A, S[13]); S[14] = fma2_(a0A, v1A, S[14]); S[15] = fma2_(a0A, v2A, S[15]);
        S[16] = fma2_(a1A, v0A, S[16]); S[17] = fma2_(a1A, v1A, S[17]); S[18] = fma2_(a1A, v2A, S[18]);
        S[19] = fma2_(a2A, v0A, S[19]); S[20] = fma2_(a2A, v1A, S[20]); S[21] = fma2_(a2A, v2A, S[21]);

        // ---- Horizontal 3-column combine: 2 shfl + 3 adds per stat -> 2 windows ----
        u64 W[NSTAT];
        #pragma unroll
        for (int k = 0; k < NSTAT; k++) {
            float s0, s1;
            upk2(S[k], s0, s1);
            const float n0 = __shfl_down_sync(0xFFFFFFFFu, s0, 1);
            const float n1 = __shfl_down_sync(0xFFFFFFFFu, s1, 1);
            const float t = s1 + n0;
            W[k] = pk2(s0 + t, t + n1);
        }

        // ---- Packed epilogue: both windows at once ----
        const float inv9f = 1.0f / 9.0f;
        const u64 INV9  = pk2(inv9f, inv9f);
        const u64 NINV9 = neg2_(INV9);
        const u64 EPS9  = pk2(1e-7f * inv9f, 1e-7f * inv9f);

        const u64 mu0 = mul2_(W[0], INV9), nmu0 = neg2_(mu0);
        const u64 mu1 = mul2_(W[1], INV9), nmu1 = neg2_(mu1);
        const u64 mu2 = mul2_(W[2], INV9), nmu2 = neg2_(mu2);

        const u64 g00 = fma2_(mu0, nmu0, fma2_(W[3], INV9, EPS9));
        const u64 g01 = fma2_(mu0, nmu1, mul2_(W[4], INV9));
        const u64 g02 = fma2_(mu0, nmu2, mul2_(W[5], INV9));
        const u64 g11 = fma2_(mu1, nmu1, fma2_(W[6], INV9, EPS9));
        const u64 g12 = fma2_(mu1, nmu2, mul2_(W[7], INV9));
        const u64 g22 = fma2_(mu2, nmu2, fma2_(W[8], INV9, EPS9));

        const u64 ng01 = neg2_(g01);
        const u64 ng02 = neg2_(g02);
        const u64 ng11 = neg2_(g11);
        const u64 ng12 = neg2_(g12);
        const u64 ng22 = neg2_(g22);

        const u64 adj00 = fma2_(g12, ng12, mul2_(g11, g22));
        const u64 adj01 = fma2_(g01, ng22, mul2_(g02, g12));   // g02*g12 - g01*g22
        const u64 adj02 = fma2_(g02, ng11, mul2_(g01, g12));   // g01*g12 - g02*g11
        const u64 adj11 = fma2_(g02, ng02, mul2_(g00, g22));
        const u64 adj12 = fma2_(g00, ng12, mul2_(g01, g02));   // g01*g02 - g00*g12
        const u64 adj22 = fma2_(g01, ng01, mul2_(g00, g11));

        const u64 det = fma2_(g00, adj00, fma2_(g01, adj01, mul2_(g02, adj02)));
        float d0, d1;
        upk2(det, d0, d1);
        const u64 invdet = pk2(1.0f / d0, 1.0f / d1);

        u64 acc9 = 0ULL;   // (0.0f, 0.0f)
        #pragma unroll
        for (int cv = 0; cv < 3; cv++) {
            const u64 s = W[9 + cv];
            const u64 y0 = fma2_(nmu0, s, W[13 + cv]);
            const u64 y1 = fma2_(nmu1, s, W[16 + cv]);
            const u64 y2 = fma2_(nmu2, s, W[19 + cv]);
            const u64 y1x2 = add2_(y1, y1);
            const u64 y2x2 = add2_(y2, y2);
            const u64 p0 = fma2_(adj02, y2x2, fma2_(adj01, y1x2, mul2_(adj00, y0)));
            const u64 p1 = fma2_(adj12, y2x2, mul2_(adj11, y1));
            const u64 p2 = mul2_(adj22, y2);
            const u64 quad = fma2_(y2, p2, fma2_(y1, p1, mul2_(y0, p0)));
            acc9 = fma2_(s, s, acc9);
            acc9 = fma2_(quad, invdet, acc9);
        }
        const u64 cpk = fma2_(acc9, NINV9, W[12]);   // Q - acc9/9, both windows

        float c_lo, c_hi;
        upk2(cpk, c_lo, c_hi);
        const int w0 = seg * WPS + 2 * lane;          // unclamped window column
        const bool prod = (lane < 31);                // lane 31 is producer-only
        if (prod && w0 < OUT_W) contrib += c_lo;
        if (prod && w0 + 1 < OUT_W) contrib += c_hi;
    }

    // ---- Block reduction: warp shuffles (deterministic fixed tree) ----
    double acc = (double)contrib;
    #pragma unroll
    for (int off = 16; off > 0; off >>= 1)
        acc += __shfl_down_sync(0xFFFFFFFFu, acc, off);

    __shared__ double warp_sums[NWARP];
    if (lane == 0) warp_sums[wid] = acc;
    __syncthreads();

    // ---- Fence-free packed-atomic finish (no release fence -> no L1 flush) ----
    if (tid == 0) {
        double bsum = 0.0;
        #pragma unroll
        for (int i = 0; i < NWARP; i++) bsum += warp_sums[i];

        const long long fx = __double2ll_rn(bsum * FIX_SCALE);
        const u64 term = (1ULL << COUNT_SHIFT) + (u64)fx;
        const u64 old = atomicAdd(&g_acc, term);

        if ((old >> COUNT_SHIFT) == (u64)(NBLK - 1)) {
            const u64 total = old + term;
            const long long value = (long long)(total - ((u64)NBLK << COUNT_SHIFT));
            out[0] = (float)((double)value * (1.0 / FIX_SCALE));
            atomicExch(&g_acc, 0ULL);   // reset for next graph replay
        }
    }
}

extern "C" void kernel_launch(void* const* d_in, const int* in_sizes, int n_in,
                              void* d_out, int out_size)
{
    const float* tgt = (const float*)d_in[0];   // target  (3, 512, 512) fp32
    const float* sty = (const float*)d_in[1];   // style   (3, 512, 512) fp32
    float* out = (float*)d_out;

    ml_pk_kernel<<<NBLK, BLOCK>>>(tgt, sty, out);
}